// round 9
// baseline (speedup 1.0000x reference)
#include <cuda_runtime.h>
#include <cuda_bf16.h>

#define N_NODES 5
#define EMB 16
#define HID 32

// ---------------------------------------------------------------------------
// Single fused kernel.
// Prologue (per block, redundant): tiny 5-node GCN -> 6x16 LUT in smem.
//   Issue cost (~1200 warp-inst/block) hides in the 90% idle issue slots of
//   the streaming phase; gs loads are issued BEFORE the prologue so their
//   latency hides under the GCN compute.
// Main phase: HBM-streaming scatter. Block tile = 2048 quads (32KB).
//   Thread t handles quads {t + u*256}: every STG.128 is a fully-coalesced
//   512B/warp stream via __stcs. Measured ceiling ~5 TB/s.
// ---------------------------------------------------------------------------
#define TPB 256
#define QPT 8
#define TILE (TPB * QPT)   // 2048 quads per block

__global__ void __launch_bounds__(TPB)
scatter_gcn(const int* __restrict__ gs,
            const float* __restrict__ emb,   // [5,16]
            const float* __restrict__ A,     // [5,5]
            const float* __restrict__ W0,    // [32,16]
            const float* __restrict__ W1,    // [32,32]
            const float* __restrict__ W2,    // [32,32]
            const float* __restrict__ Wf,    // [16,32]
            const float* __restrict__ bf,    // [16]
            float4* __restrict__ out,
            int nquads)
{
    // ---- weight staging + GCN intermediates ----
    __shared__ float sE[N_NODES * EMB];
    __shared__ float sA[N_NODES * N_NODES];
    __shared__ float sW0[HID * EMB];
    __shared__ float sW1[HID * HID];
    __shared__ float sW2[HID * HID];
    __shared__ float sWf[EMB * HID];
    __shared__ float sbf[EMB];
    __shared__ float x0[N_NODES][EMB];
    __shared__ float h[N_NODES][HID];
    __shared__ float y[N_NODES][HID];
    __shared__ float4 slut[6 * 4];   // final LUT: 6 rows x 4 quads

    const int t = threadIdx.x;
    const int base = blockIdx.x * TILE + t;   // quad index, iter 0
    const bool fast = (base + (QPT - 1) * TPB < nquads);

    // ---- issue gs loads FIRST (independent of LUT; latency hides under GCN)
    int c[QPT];
    if (fast) {
        const int* __restrict__ g = gs + (base >> 2);
        #pragma unroll
        for (int u = 0; u < QPT; u++) c[u] = __ldg(g + u * (TPB >> 2));
    }

    // ---- GCN prologue (weights prefetched in parallel: one load latency) ----
    for (int i = t; i < N_NODES * EMB; i += TPB) sE[i] = emb[i];
    for (int i = t; i < N_NODES * N_NODES; i += TPB) sA[i] = A[i];
    for (int i = t; i < HID * EMB; i += TPB) sW0[i] = W0[i];
    for (int i = t; i < HID * HID; i += TPB) sW1[i] = W1[i];
    for (int i = t; i < HID * HID; i += TPB) sW2[i] = W2[i];
    for (int i = t; i < EMB * HID; i += TPB) sWf[i] = Wf[i];
    for (int i = t; i < EMB; i += TPB) sbf[i] = bf[i];
    __syncthreads();

    // x0 = A @ emb_table  [5,16]
    if (t < N_NODES * EMB) {
        int i = t / EMB, j = t % EMB;
        float s = 0.f;
        #pragma unroll
        for (int k = 0; k < N_NODES; k++) s += sA[i * N_NODES + k] * sE[k * EMB + j];
        x0[i][j] = s;
    }
    __syncthreads();

    // h = relu(x0 @ W0^T)  [5,32]
    if (t < N_NODES * HID) {
        int i = t / HID, o = t % HID;
        float s = 0.f;
        #pragma unroll
        for (int j = 0; j < EMB; j++) s += x0[i][j] * sW0[o * EMB + j];
        h[i][o] = fmaxf(s, 0.f);
    }
    __syncthreads();

    // round 1: y = A@h ; h = relu(y @ W1^T)
    if (t < N_NODES * HID) {
        int i = t / HID, o = t % HID;
        float s = 0.f;
        #pragma unroll
        for (int k = 0; k < N_NODES; k++) s += sA[i * N_NODES + k] * h[k][o];
        y[i][o] = s;
    }
    __syncthreads();
    if (t < N_NODES * HID) {
        int i = t / HID, o = t % HID;
        float s = 0.f;
        #pragma unroll
        for (int j = 0; j < HID; j++) s += y[i][j] * sW1[o * HID + j];
        h[i][o] = fmaxf(s, 0.f);
    }
    __syncthreads();

    // round 2: y = A@h ; h = relu(y @ W2^T)
    if (t < N_NODES * HID) {
        int i = t / HID, o = t % HID;
        float s = 0.f;
        #pragma unroll
        for (int k = 0; k < N_NODES; k++) s += sA[i * N_NODES + k] * h[k][o];
        y[i][o] = s;
    }
    __syncthreads();
    if (t < N_NODES * HID) {
        int i = t / HID, o = t % HID;
        float s = 0.f;
        #pragma unroll
        for (int j = 0; j < HID; j++) s += y[i][j] * sW2[o * HID + j];
        h[i][o] = fmaxf(s, 0.f);
    }
    __syncthreads();

    // LUT rows 1..5 : h @ Wf^T + bf ; row 0 : emb_table row 0
    float* slutf = reinterpret_cast<float*>(slut);
    if (t < N_NODES * EMB) {
        int i = t / EMB, e = t % EMB;
        float s = sbf[e];
        #pragma unroll
        for (int j = 0; j < HID; j++) s += h[i][j] * sWf[e * HID + j];
        slutf[(i + 1) * EMB + e] = s;
    }
    if (t < EMB) slutf[t] = sE[t];
    __syncthreads();

    // ---- streaming scatter ----
    const int q = t & 3;                       // lane-within-cell (TILE%4==0)
    const float4* __restrict__ lutq = slut + q;
    float4* __restrict__ o = out + base;

    if (fast) {
        #pragma unroll
        for (int u = 0; u < QPT; u++) {
            float4 v = lutq[c[u] * 4];
            __stcs(o + u * TPB, v);
        }
    } else {
        #pragma unroll
        for (int u = 0; u < QPT; u++) {
            int idx = base + u * TPB;
            if (idx < nquads) {
                int cc = __ldg(gs + (idx >> 2));
                __stcs(o + u * TPB, lutq[cc * 4]);
            }
        }
    }
}

// ---------------------------------------------------------------------------
extern "C" void kernel_launch(void* const* d_in, const int* in_sizes, int n_in,
                              void* d_out, int out_size)
{
    const int*   gs  = (const int*)d_in[0];    // game_state [256,128,128]
    const float* emb = (const float*)d_in[1];  // [5,16]
    const float* A   = (const float*)d_in[2];  // [5,5]
    const float* W0  = (const float*)d_in[3];  // [32,16]
    const float* W1  = (const float*)d_in[4];  // [32,32]
    const float* W2  = (const float*)d_in[5];  // [32,32]
    const float* Wf  = (const float*)d_in[6];  // [16,32]
    const float* bf  = (const float*)d_in[7];  // [16]
    float4* out = (float4*)d_out;

    const int ncells = in_sizes[0];            // 4,194,304
    const int nquads = ncells * 4;             // 16,777,216 float4 stores

    const int blocks = (nquads + TILE - 1) / TILE;   // 8192
    scatter_gcn<<<blocks, TPB>>>(gs, emb, A, W0, W1, W2, Wf, bf, out, nquads);
}

// round 10
// speedup vs baseline: 6.8652x; 6.8652x over previous
#include <cuda_runtime.h>
#include <cuda_bf16.h>

#define N_NODES 5
#define EMB 16
#define HID 32

// ---------------------------------------------------------------------------
// Single fused kernel.
// Prologue (per block, redundant): 5-node GCN -> 6x16 LUT in smem, with all
//   weights staged TRANSPOSED + PADDED so every LDS in the matmul stages is
//   bank-conflict-free (R9's 32-way conflicts were the 440us disaster).
// Main phase: HBM-streaming scatter, TILE = 4096 quads (64KB) per block.
//   Thread t handles quads {t + u*512}: fully-coalesced STG.128 via __stcs.
// ---------------------------------------------------------------------------
#define TPB 512
#define QPT 8
#define TILE (TPB * QPT)   // 4096 quads per block

__global__ void __launch_bounds__(TPB)
scatter_gcn(const int* __restrict__ gs,
            const float* __restrict__ emb,   // [5,16]
            const float* __restrict__ A,     // [5,5]
            const float* __restrict__ W0,    // [32,16]
            const float* __restrict__ W1,    // [32,32]
            const float* __restrict__ W2,    // [32,32]
            const float* __restrict__ Wf,    // [16,32]
            const float* __restrict__ bf,    // [16]
            float4* __restrict__ out,
            int nquads)
{
    // ---- transposed, padded weight staging + GCN intermediates ----
    __shared__ float sE[N_NODES * EMB];        // [5,16]
    __shared__ float sA[N_NODES * N_NODES];    // [5,5]
    __shared__ float sW0T[EMB * 33];           // W0T[j][o], stride 33
    __shared__ float sW1T[HID * 33];           // W1T[j][o], stride 33
    __shared__ float sW2T[HID * 33];           // W2T[j][o], stride 33
    __shared__ float sWfT[HID * 17];           // WfT[j][e], stride 17
    __shared__ float sbf[EMB];
    __shared__ float x0[N_NODES][EMB];
    __shared__ float h[N_NODES][HID];
    __shared__ float y[N_NODES][HID];
    __shared__ float4 slut[6 * 4];             // final LUT: 6 rows x 4 quads

    const int t = threadIdx.x;
    const int base = blockIdx.x * TILE + t;    // quad index, iter 0
    const bool fast = (base + (QPT - 1) * TPB < nquads);

    // ---- issue gs loads FIRST (latency hides under the GCN prologue) ----
    int c[QPT];
    if (fast) {
        const int* __restrict__ g = gs + (base >> 2);
        #pragma unroll
        for (int u = 0; u < QPT; u++) c[u] = __ldg(g + u * (TPB >> 2));
    }

    // ---- stage weights (coalesced global reads, conflict-free STS) ----
    for (int i = t; i < N_NODES * EMB; i += TPB) sE[i] = emb[i];
    for (int i = t; i < N_NODES * N_NODES; i += TPB) sA[i] = A[i];
    for (int i = t; i < HID * EMB; i += TPB) {      // W0[o][j] -> sW0T[j][o]
        int o = i / EMB, j = i % EMB;
        sW0T[j * 33 + o] = W0[i];
    }
    for (int i = t; i < HID * HID; i += TPB) {      // W1[o][j] -> sW1T[j][o]
        int o = i / HID, j = i % HID;
        sW1T[j * 33 + o] = W1[i];
    }
    for (int i = t; i < HID * HID; i += TPB) {      // W2[o][j] -> sW2T[j][o]
        int o = i / HID, j = i % HID;
        sW2T[j * 33 + o] = W2[i];
    }
    for (int i = t; i < EMB * HID; i += TPB) {      // Wf[e][j] -> sWfT[j][e]
        int e = i / HID, j = i % HID;
        sWfT[j * 17 + e] = Wf[i];
    }
    for (int i = t; i < EMB; i += TPB) sbf[i] = bf[i];
    __syncthreads();

    // x0 = A @ emb_table  [5,16]   (broadcast reads)
    if (t < N_NODES * EMB) {
        int i = t / EMB, j = t % EMB;
        float s = 0.f;
        #pragma unroll
        for (int k = 0; k < N_NODES; k++) s += sA[i * N_NODES + k] * sE[k * EMB + j];
        x0[i][j] = s;
    }
    __syncthreads();

    // h = relu(x0 @ W0^T)  [5,32]  (lane = o; sW0T read conflict-free)
    if (t < N_NODES * HID) {
        int i = t / HID, o = t % HID;
        float s = 0.f;
        #pragma unroll
        for (int j = 0; j < EMB; j++) s += x0[i][j] * sW0T[j * 33 + o];
        h[i][o] = fmaxf(s, 0.f);
    }
    __syncthreads();

    // round 1: y = A@h ; h = relu(y @ W1^T)
    if (t < N_NODES * HID) {
        int i = t / HID, o = t % HID;
        float s = 0.f;
        #pragma unroll
        for (int k = 0; k < N_NODES; k++) s += sA[i * N_NODES + k] * h[k][o];
        y[i][o] = s;
    }
    __syncthreads();
    if (t < N_NODES * HID) {
        int i = t / HID, o = t % HID;
        float s = 0.f;
        #pragma unroll
        for (int j = 0; j < HID; j++) s += y[i][j] * sW1T[j * 33 + o];
        h[i][o] = fmaxf(s, 0.f);
    }
    __syncthreads();

    // round 2: y = A@h ; h = relu(y @ W2^T)
    if (t < N_NODES * HID) {
        int i = t / HID, o = t % HID;
        float s = 0.f;
        #pragma unroll
        for (int k = 0; k < N_NODES; k++) s += sA[i * N_NODES + k] * h[k][o];
        y[i][o] = s;
    }
    __syncthreads();
    if (t < N_NODES * HID) {
        int i = t / HID, o = t % HID;
        float s = 0.f;
        #pragma unroll
        for (int j = 0; j < HID; j++) s += y[i][j] * sW2T[j * 33 + o];
        h[i][o] = fmaxf(s, 0.f);
    }
    __syncthreads();

    // LUT rows 1..5 : h @ Wf^T + bf ; row 0 : emb_table row 0
    float* slutf = reinterpret_cast<float*>(slut);
    if (t < N_NODES * EMB) {
        int i = t / EMB, e = t % EMB;
        float s = sbf[e];
        #pragma unroll
        for (int j = 0; j < HID; j++) s += h[i][j] * sWfT[j * 17 + e];
        slutf[(i + 1) * EMB + e] = s;
    }
    if (t < EMB) slutf[t] = sE[t];
    __syncthreads();

    // ---- streaming scatter ----
    const int q = t & 3;                       // lane-within-cell (TILE%4==0)
    const float4* __restrict__ lutq = slut + q;
    float4* __restrict__ o = out + base;

    if (fast) {
        #pragma unroll
        for (int u = 0; u < QPT; u++) {
            float4 v = lutq[c[u] * 4];
            __stcs(o + u * TPB, v);
        }
    } else {
        #pragma unroll
        for (int u = 0; u < QPT; u++) {
            int idx = base + u * TPB;
            if (idx < nquads) {
                int cc = __ldg(gs + (idx >> 2));
                __stcs(o + u * TPB, lutq[cc * 4]);
            }
        }
    }
}

// ---------------------------------------------------------------------------
extern "C" void kernel_launch(void* const* d_in, const int* in_sizes, int n_in,
                              void* d_out, int out_size)
{
    const int*   gs  = (const int*)d_in[0];    // game_state [256,128,128]
    const float* emb = (const float*)d_in[1];  // [5,16]
    const float* A   = (const float*)d_in[2];  // [5,5]
    const float* W0  = (const float*)d_in[3];  // [32,16]
    const float* W1  = (const float*)d_in[4];  // [32,32]
    const float* W2  = (const float*)d_in[5];  // [32,32]
    const float* Wf  = (const float*)d_in[6];  // [16,32]
    const float* bf  = (const float*)d_in[7];  // [16]
    float4* out = (float4*)d_out;

    const int ncells = in_sizes[0];            // 4,194,304
    const int nquads = ncells * 4;             // 16,777,216 float4 stores

    const int blocks = (nquads + TILE - 1) / TILE;   // 4096
    scatter_gcn<<<blocks, TPB>>>(gs, emb, A, W0, W1, W2, Wf, bf, out, nquads);
}

// round 11
// speedup vs baseline: 8.1621x; 1.1889x over previous
#include <cuda_runtime.h>
#include <cuda_bf16.h>

#define N_NODES 5
#define EMB 16
#define HID 32

// ---------------------------------------------------------------------------
// Single fused PERSISTENT kernel.
// Prologue (once per resident block): 5-node GCN -> 6x16 LUT in smem, all
//   weights staged transposed+padded so every LDS is bank-conflict-free.
// Main phase: grid-stride loop over 2048-quad tiles (R8's proven streaming
//   shape: thread t handles quads {t + u*256}, coalesced STG.128 via __stcs).
//   gs indices for the next tile are prefetched before storing the current
//   tile, so inter-tile load latency stays hidden.
// One wave (1184 blocks) => prologue cost paid once, not once per wave.
// ---------------------------------------------------------------------------
#define TPB 256
#define QPT 8
#define TILE (TPB * QPT)   // 2048 quads per tile

__global__ void __launch_bounds__(TPB)
scatter_gcn(const int* __restrict__ gs,
            const float* __restrict__ emb,   // [5,16]
            const float* __restrict__ A,     // [5,5]
            const float* __restrict__ W0,    // [32,16]
            const float* __restrict__ W1,    // [32,32]
            const float* __restrict__ W2,    // [32,32]
            const float* __restrict__ Wf,    // [16,32]
            const float* __restrict__ bf,    // [16]
            float4* __restrict__ out,
            int nquads, int ntiles)
{
    __shared__ float sE[N_NODES * EMB];
    __shared__ float sA[N_NODES * N_NODES];
    __shared__ float sW0T[EMB * 33];           // W0T[j][o]
    __shared__ float sW1T[HID * 33];           // W1T[j][o]
    __shared__ float sW2T[HID * 33];           // W2T[j][o]
    __shared__ float sWfT[HID * 17];           // WfT[j][e]
    __shared__ float sbf[EMB];
    __shared__ float x0[N_NODES][EMB];
    __shared__ float h[N_NODES][HID];
    __shared__ float y[N_NODES][HID];
    __shared__ float4 slut[6 * 4];             // final LUT: 6 rows x 4 quads

    const int t = threadIdx.x;

    // ---- prefetch gs for this block's FIRST tile (hides under prologue) ----
    int tile = blockIdx.x;
    int c[QPT];
    if (tile < ntiles) {
        const int* __restrict__ g = gs + ((tile * TILE + t) >> 2);
        #pragma unroll
        for (int u = 0; u < QPT; u++) c[u] = __ldg(g + u * (TPB >> 2));
    }

    // ---- stage weights (conflict-free transposed STS) ----
    for (int i = t; i < N_NODES * EMB; i += TPB) sE[i] = emb[i];
    for (int i = t; i < N_NODES * N_NODES; i += TPB) sA[i] = A[i];
    for (int i = t; i < HID * EMB; i += TPB) {
        int o = i / EMB, j = i % EMB;
        sW0T[j * 33 + o] = W0[i];
    }
    for (int i = t; i < HID * HID; i += TPB) {
        int o = i / HID, j = i % HID;
        sW1T[j * 33 + o] = W1[i];
    }
    for (int i = t; i < HID * HID; i += TPB) {
        int o = i / HID, j = i % HID;
        sW2T[j * 33 + o] = W2[i];
    }
    for (int i = t; i < EMB * HID; i += TPB) {
        int e = i / HID, j = i % HID;
        sWfT[j * 17 + e] = Wf[i];
    }
    for (int i = t; i < EMB; i += TPB) sbf[i] = bf[i];
    __syncthreads();

    // ---- GCN stages (all LDS conflict-free) ----
    if (t < N_NODES * EMB) {
        int i = t / EMB, j = t % EMB;
        float s = 0.f;
        #pragma unroll
        for (int k = 0; k < N_NODES; k++) s += sA[i * N_NODES + k] * sE[k * EMB + j];
        x0[i][j] = s;
    }
    __syncthreads();

    if (t < N_NODES * HID) {
        int i = t / HID, o = t % HID;
        float s = 0.f;
        #pragma unroll
        for (int j = 0; j < EMB; j++) s += x0[i][j] * sW0T[j * 33 + o];
        h[i][o] = fmaxf(s, 0.f);
    }
    __syncthreads();

    if (t < N_NODES * HID) {
        int i = t / HID, o = t % HID;
        float s = 0.f;
        #pragma unroll
        for (int k = 0; k < N_NODES; k++) s += sA[i * N_NODES + k] * h[k][o];
        y[i][o] = s;
    }
    __syncthreads();
    if (t < N_NODES * HID) {
        int i = t / HID, o = t % HID;
        float s = 0.f;
        #pragma unroll
        for (int j = 0; j < HID; j++) s += y[i][j] * sW1T[j * 33 + o];
        h[i][o] = fmaxf(s, 0.f);
    }
    __syncthreads();

    if (t < N_NODES * HID) {
        int i = t / HID, o = t % HID;
        float s = 0.f;
        #pragma unroll
        for (int k = 0; k < N_NODES; k++) s += sA[i * N_NODES + k] * h[k][o];
        y[i][o] = s;
    }
    __syncthreads();
    if (t < N_NODES * HID) {
        int i = t / HID, o = t % HID;
        float s = 0.f;
        #pragma unroll
        for (int j = 0; j < HID; j++) s += y[i][j] * sW2T[j * 33 + o];
        h[i][o] = fmaxf(s, 0.f);
    }
    __syncthreads();

    float* slutf = reinterpret_cast<float*>(slut);
    if (t < N_NODES * EMB) {
        int i = t / EMB, e = t % EMB;
        float s = sbf[e];
        #pragma unroll
        for (int j = 0; j < HID; j++) s += h[i][j] * sWfT[j * 17 + e];
        slutf[(i + 1) * EMB + e] = s;
    }
    if (t < EMB) slutf[t] = sE[t];
    __syncthreads();

    // ---- persistent streaming loop over tiles (double-buffered gs) ----
    const int q = t & 3;
    const float4* __restrict__ lutq = slut + q;

    while (tile < ntiles) {
        const int next = tile + gridDim.x;

        // prefetch next tile's indices before storing this one
        int cn[QPT];
        if (next < ntiles) {
            const int* __restrict__ g = gs + ((next * TILE + t) >> 2);
            #pragma unroll
            for (int u = 0; u < QPT; u++) cn[u] = __ldg(g + u * (TPB >> 2));
        }

        const int base = tile * TILE + t;
        float4* __restrict__ o = out + base;
        if (base + (QPT - 1) * TPB < nquads) {
            #pragma unroll
            for (int u = 0; u < QPT; u++) {
                float4 v = lutq[c[u] * 4];
                __stcs(o + u * TPB, v);
            }
        } else {
            #pragma unroll
            for (int u = 0; u < QPT; u++) {
                int idx = base + u * TPB;
                if (idx < nquads) {
                    int cc = __ldg(gs + (idx >> 2));
                    __stcs(o + u * TPB, lutq[cc * 4]);
                }
            }
        }

        #pragma unroll
        for (int u = 0; u < QPT; u++) c[u] = cn[u];
        tile = next;
    }
}

// ---------------------------------------------------------------------------
extern "C" void kernel_launch(void* const* d_in, const int* in_sizes, int n_in,
                              void* d_out, int out_size)
{
    const int*   gs  = (const int*)d_in[0];    // game_state [256,128,128]
    const float* emb = (const float*)d_in[1];  // [5,16]
    const float* A   = (const float*)d_in[2];  // [5,5]
    const float* W0  = (const float*)d_in[3];  // [32,16]
    const float* W1  = (const float*)d_in[4];  // [32,32]
    const float* W2  = (const float*)d_in[5];  // [32,32]
    const float* Wf  = (const float*)d_in[6];  // [16,32]
    const float* bf  = (const float*)d_in[7];  // [16]
    float4* out = (float4*)d_out;

    const int ncells = in_sizes[0];            // 4,194,304
    const int nquads = ncells * 4;             // 16,777,216 float4 stores
    const int ntiles = (nquads + TILE - 1) / TILE;   // 8192

    // one wave: 148 SMs x 8 resident 256-thread blocks
    int blocks = 148 * 8;
    if (blocks > ntiles) blocks = ntiles;

    scatter_gcn<<<blocks, TPB>>>(gs, emb, A, W0, W1, W2, Wf, bf, out,
                                 nquads, ntiles);
}

// round 13
// speedup vs baseline: 8.4543x; 1.0358x over previous
#include <cuda_runtime.h>
#include <cuda_bf16.h>

#define N_NODES 5
#define EMB 16
#define HID 32

// ---------------------------------------------------------------------------
// Single fused PERSISTENT kernel, one true wave.
// Prologue (once per block, all concurrent at t=0): 5-node GCN -> 6x16 LUT in
//   smem; weights staged transposed+padded so every LDS is conflict-free.
// Main: grid-stride loop over 2048-quad tiles (proven 45.4us streaming shape):
//   thread t handles quads {t + u*256}, coalesced STG.128 via __stcs.
//   gs is L2-resident during timed replays; 8-way MLP loads at each tile head
//   hide under the 7 sibling blocks' store streams — no double buffer, so
//   regs stay <=32 and 8 blocks/SM actually fit (R11's 38 regs -> 6 blocks).
// ---------------------------------------------------------------------------
#define TPB 256
#define QPT 8
#define TILE (TPB * QPT)   // 2048 quads per tile

__global__ void __launch_bounds__(TPB, 8)
scatter_gcn(const int* __restrict__ gs,
            const float* __restrict__ emb,   // [5,16]
            const float* __restrict__ A,     // [5,5]
            const float* __restrict__ W0,    // [32,16]
            const float* __restrict__ W1,    // [32,32]
            const float* __restrict__ W2,    // [32,32]
            const float* __restrict__ Wf,    // [16,32]
            const float* __restrict__ bf,    // [16]
            float4* __restrict__ out,
            int nquads, int ntiles)
{
    __shared__ float sE[N_NODES * EMB];
    __shared__ float sA[N_NODES * N_NODES];
    __shared__ float sW0T[EMB * 33];           // W0T[j][o]
    __shared__ float sW1T[HID * 33];           // W1T[j][o]
    __shared__ float sW2T[HID * 33];           // W2T[j][o]
    __shared__ float sWfT[HID * 17];           // WfT[j][e]
    __shared__ float sbf[EMB];
    __shared__ float x0[N_NODES][EMB];
    __shared__ float h[N_NODES][HID];
    __shared__ float y[N_NODES][HID];
    __shared__ float4 slut[6 * 4];             // final LUT: 6 rows x 4 quads

    const int t = threadIdx.x;

    // ---- stage weights (conflict-free transposed STS) ----
    for (int i = t; i < N_NODES * EMB; i += TPB) sE[i] = emb[i];
    for (int i = t; i < N_NODES * N_NODES; i += TPB) sA[i] = A[i];
    for (int i = t; i < HID * EMB; i += TPB) {
        int o = i / EMB, j = i % EMB;
        sW0T[j * 33 + o] = W0[i];
    }
    for (int i = t; i < HID * HID; i += TPB) {
        int o = i / HID, j = i % HID;
        sW1T[j * 33 + o] = W1[i];
    }
    for (int i = t; i < HID * HID; i += TPB) {
        int o = i / HID, j = i % HID;
        sW2T[j * 33 + o] = W2[i];
    }
    for (int i = t; i < EMB * HID; i += TPB) {
        int e = i / HID, j = i % HID;
        sWfT[j * 17 + e] = Wf[i];
    }
    for (int i = t; i < EMB; i += TPB) sbf[i] = bf[i];
    __syncthreads();

    // ---- GCN stages (all LDS conflict-free) ----
    if (t < N_NODES * EMB) {
        int i = t / EMB, j = t % EMB;
        float s = 0.f;
        #pragma unroll
        for (int k = 0; k < N_NODES; k++) s += sA[i * N_NODES + k] * sE[k * EMB + j];
        x0[i][j] = s;
    }
    __syncthreads();

    if (t < N_NODES * HID) {
        int i = t / HID, o = t % HID;
        float s = 0.f;
        #pragma unroll
        for (int j = 0; j < EMB; j++) s += x0[i][j] * sW0T[j * 33 + o];
        h[i][o] = fmaxf(s, 0.f);
    }
    __syncthreads();

    if (t < N_NODES * HID) {
        int i = t / HID, o = t % HID;
        float s = 0.f;
        #pragma unroll
        for (int k = 0; k < N_NODES; k++) s += sA[i * N_NODES + k] * h[k][o];
        y[i][o] = s;
    }
    __syncthreads();
    if (t < N_NODES * HID) {
        int i = t / HID, o = t % HID;
        float s = 0.f;
        #pragma unroll
        for (int j = 0; j < HID; j++) s += y[i][j] * sW1T[j * 33 + o];
        h[i][o] = fmaxf(s, 0.f);
    }
    __syncthreads();

    if (t < N_NODES * HID) {
        int i = t / HID, o = t % HID;
        float s = 0.f;
        #pragma unroll
        for (int k = 0; k < N_NODES; k++) s += sA[i * N_NODES + k] * h[k][o];
        y[i][o] = s;
    }
    __syncthreads();
    if (t < N_NODES * HID) {
        int i = t / HID, o = t % HID;
        float s = 0.f;
        #pragma unroll
        for (int j = 0; j < HID; j++) s += y[i][j] * sW2T[j * 33 + o];
        h[i][o] = fmaxf(s, 0.f);
    }
    __syncthreads();

    float* slutf = reinterpret_cast<float*>(slut);
    if (t < N_NODES * EMB) {
        int i = t / EMB, e = t % EMB;
        float s = sbf[e];
        #pragma unroll
        for (int j = 0; j < HID; j++) s += h[i][j] * sWfT[j * 17 + e];
        slutf[(i + 1) * EMB + e] = s;
    }
    if (t < EMB) slutf[t] = sE[t];
    __syncthreads();

    // ---- persistent streaming loop over tiles ----
    const int q = t & 3;                       // lane-within-cell (TILE%4==0)
    const float4* __restrict__ lutq = slut + q;

    for (int tile = blockIdx.x; tile < ntiles; tile += gridDim.x) {
        const int base = tile * TILE + t;
        float4* __restrict__ o = out + base;

        if (base + (QPT - 1) * TPB < nquads) {
            // fast path: 8 independent L2-hot loads, then 8 coalesced stores
            const int* __restrict__ g = gs + (base >> 2);
            int c[QPT];
            #pragma unroll
            for (int u = 0; u < QPT; u++) c[u] = __ldg(g + u * (TPB >> 2));
            #pragma unroll
            for (int u = 0; u < QPT; u++) {
                float4 v = lutq[c[u] * 4];
                __stcs(o + u * TPB, v);
            }
        } else {
            #pragma unroll
            for (int u = 0; u < QPT; u++) {
                int idx = base + u * TPB;
                if (idx < nquads) {
                    int cc = __ldg(gs + (idx >> 2));
                    __stcs(o + u * TPB, lutq[cc * 4]);
                }
            }
        }
    }
}

// ---------------------------------------------------------------------------
extern "C" void kernel_launch(void* const* d_in, const int* in_sizes, int n_in,
                              void* d_out, int out_size)
{
    const int*   gs  = (const int*)d_in[0];    // game_state [256,128,128]
    const float* emb = (const float*)d_in[1];  // [5,16]
    const float* A   = (const float*)d_in[2];  // [5,5]
    const float* W0  = (const float*)d_in[3];  // [32,16]
    const float* W1  = (const float*)d_in[4];  // [32,32]
    const float* W2  = (const float*)d_in[5];  // [32,32]
    const float* Wf  = (const float*)d_in[6];  // [16,32]
    const float* bf  = (const float*)d_in[7];  // [16]
    float4* out = (float4*)d_out;

    const int ncells = in_sizes[0];            // 4,194,304
    const int nquads = ncells * 4;             // 16,777,216 float4 stores
    const int ntiles = (nquads + TILE - 1) / TILE;   // 8192

    // one true wave: 148 SMs x 8 resident 256-thread blocks (regs forced <=32)
    int blocks = 148 * 8;
    if (blocks > ntiles) blocks = ntiles;

    scatter_gcn<<<blocks, TPB>>>(gs, emb, A, W0, W1, W2, Wf, bf, out,
                                 nquads, ntiles);
}

// round 14
// speedup vs baseline: 8.5280x; 1.0087x over previous
#include <cuda_runtime.h>
#include <cuda_bf16.h>

#define N_NODES 5
#define EMB 16
#define HID 32

// Global tile counter — reset to 0 each launch via a captured memset node.
__device__ int g_ctr;

// ---------------------------------------------------------------------------
// Single fused PERSISTENT kernel, one wave, DYNAMIC tile scheduling.
// Prologue (once per block): 5-node GCN -> 6x16 LUT in smem; weights staged
//   transposed+padded so every LDS is bank-conflict-free.
// Main: loop over 2048-quad tiles fetched from a global atomic counter.
//   The next tile id is prefetched (thread 0, double-buffered in smem) while
//   the current tile streams, hiding ATOMG latency. Perfect load balance:
//   late-prologue blocks just take later tiles; tail imbalance <= 1 tile.
// Streaming shape per tile: thread t handles quads {t + u*256}; coalesced
//   STG.128 via __stcs at the measured ~5 TB/s write ceiling.
// ---------------------------------------------------------------------------
#define TPB 256
#define QPT 8
#define TILE (TPB * QPT)   // 2048 quads per tile

__global__ void __launch_bounds__(TPB, 8)
scatter_gcn(const int* __restrict__ gs,
            const float* __restrict__ emb,   // [5,16]
            const float* __restrict__ A,     // [5,5]
            const float* __restrict__ W0,    // [32,16]
            const float* __restrict__ W1,    // [32,32]
            const float* __restrict__ W2,    // [32,32]
            const float* __restrict__ Wf,    // [16,32]
            const float* __restrict__ bf,    // [16]
            float4* __restrict__ out,
            int nquads, int ntiles)
{
    __shared__ float sE[N_NODES * EMB];
    __shared__ float sA[N_NODES * N_NODES];
    __shared__ float sW0T[EMB * 33];           // W0T[j][o]
    __shared__ float sW1T[HID * 33];           // W1T[j][o]
    __shared__ float sW2T[HID * 33];           // W2T[j][o]
    __shared__ float sWfT[HID * 17];           // WfT[j][e]
    __shared__ float sbf[EMB];
    __shared__ float x0[N_NODES][EMB];
    __shared__ float h[N_NODES][HID];
    __shared__ float y[N_NODES][HID];
    __shared__ float4 slut[6 * 4];             // final LUT: 6 rows x 4 quads
    __shared__ int s_tile[2];                  // double-buffered tile ids

    const int t = threadIdx.x;

    // ---- fetch this block's FIRST tile id (latency hides under prologue) ----
    if (t == 0) s_tile[0] = atomicAdd(&g_ctr, 1);

    // ---- stage weights (conflict-free transposed STS) ----
    for (int i = t; i < N_NODES * EMB; i += TPB) sE[i] = emb[i];
    for (int i = t; i < N_NODES * N_NODES; i += TPB) sA[i] = A[i];
    for (int i = t; i < HID * EMB; i += TPB) {
        int o = i / EMB, j = i % EMB;
        sW0T[j * 33 + o] = W0[i];
    }
    for (int i = t; i < HID * HID; i += TPB) {
        int o = i / HID, j = i % HID;
        sW1T[j * 33 + o] = W1[i];
    }
    for (int i = t; i < HID * HID; i += TPB) {
        int o = i / HID, j = i % HID;
        sW2T[j * 33 + o] = W2[i];
    }
    for (int i = t; i < EMB * HID; i += TPB) {
        int e = i / HID, j = i % HID;
        sWfT[j * 17 + e] = Wf[i];
    }
    for (int i = t; i < EMB; i += TPB) sbf[i] = bf[i];
    __syncthreads();

    // ---- GCN stages (all LDS conflict-free) ----
    if (t < N_NODES * EMB) {
        int i = t / EMB, j = t % EMB;
        float s = 0.f;
        #pragma unroll
        for (int k = 0; k < N_NODES; k++) s += sA[i * N_NODES + k] * sE[k * EMB + j];
        x0[i][j] = s;
    }
    __syncthreads();

    if (t < N_NODES * HID) {
        int i = t / HID, o = t % HID;
        float s = 0.f;
        #pragma unroll
        for (int j = 0; j < EMB; j++) s += x0[i][j] * sW0T[j * 33 + o];
        h[i][o] = fmaxf(s, 0.f);
    }
    __syncthreads();

    if (t < N_NODES * HID) {
        int i = t / HID, o = t % HID;
        float s = 0.f;
        #pragma unroll
        for (int k = 0; k < N_NODES; k++) s += sA[i * N_NODES + k] * h[k][o];
        y[i][o] = s;
    }
    __syncthreads();
    if (t < N_NODES * HID) {
        int i = t / HID, o = t % HID;
        float s = 0.f;
        #pragma unroll
        for (int j = 0; j < HID; j++) s += y[i][j] * sW1T[j * 33 + o];
        h[i][o] = fmaxf(s, 0.f);
    }
    __syncthreads();

    if (t < N_NODES * HID) {
        int i = t / HID, o = t % HID;
        float s = 0.f;
        #pragma unroll
        for (int k = 0; k < N_NODES; k++) s += sA[i * N_NODES + k] * h[k][o];
        y[i][o] = s;
    }
    __syncthreads();
    if (t < N_NODES * HID) {
        int i = t / HID, o = t % HID;
        float s = 0.f;
        #pragma unroll
        for (int j = 0; j < HID; j++) s += y[i][j] * sW2T[j * 33 + o];
        h[i][o] = fmaxf(s, 0.f);
    }
    __syncthreads();

    float* slutf = reinterpret_cast<float*>(slut);
    if (t < N_NODES * EMB) {
        int i = t / EMB, e = t % EMB;
        float s = sbf[e];
        #pragma unroll
        for (int j = 0; j < HID; j++) s += h[i][j] * sWfT[j * 17 + e];
        slutf[(i + 1) * EMB + e] = s;
    }
    if (t < EMB) slutf[t] = sE[t];
    __syncthreads();   // LUT ready; also publishes s_tile[0]

    // ---- persistent streaming loop, dynamically scheduled tiles ----
    const int q = t & 3;                       // lane-within-cell (TILE%4==0)
    const float4* __restrict__ lutq = slut + q;

    int p = 0;
    int tile = s_tile[0];
    while (tile < ntiles) {
        // prefetch next tile id into the other buffer (hides ATOMG latency)
        if (t == 0) s_tile[p ^ 1] = atomicAdd(&g_ctr, 1);

        const int base = tile * TILE + t;
        float4* __restrict__ o = out + base;

        if (base + (QPT - 1) * TPB < nquads) {
            // fast path: 8 independent loads, then 8 coalesced streaming stores
            const int* __restrict__ g = gs + (base >> 2);
            int c[QPT];
            #pragma unroll
            for (int u = 0; u < QPT; u++) c[u] = __ldg(g + u * (TPB >> 2));
            #pragma unroll
            for (int u = 0; u < QPT; u++) {
                float4 v = lutq[c[u] * 4];
                __stcs(o + u * TPB, v);
            }
        } else {
            #pragma unroll
            for (int u = 0; u < QPT; u++) {
                int idx = base + u * TPB;
                if (idx < nquads) {
                    int cc = __ldg(gs + (idx >> 2));
                    __stcs(o + u * TPB, lutq[cc * 4]);
                }
            }
        }

        __syncthreads();           // next tile id visible to all threads
        p ^= 1;
        tile = s_tile[p];
    }
}

// ---------------------------------------------------------------------------
extern "C" void kernel_launch(void* const* d_in, const int* in_sizes, int n_in,
                              void* d_out, int out_size)
{
    const int*   gs  = (const int*)d_in[0];    // game_state [256,128,128]
    const float* emb = (const float*)d_in[1];  // [5,16]
    const float* A   = (const float*)d_in[2];  // [5,5]
    const float* W0  = (const float*)d_in[3];  // [32,16]
    const float* W1  = (const float*)d_in[4];  // [32,32]
    const float* W2  = (const float*)d_in[5];  // [32,32]
    const float* Wf  = (const float*)d_in[6];  // [16,32]
    const float* bf  = (const float*)d_in[7];  // [16]
    float4* out = (float4*)d_out;

    const int ncells = in_sizes[0];            // 4,194,304
    const int nquads = ncells * 4;             // 16,777,216 float4 stores
    const int ntiles = (nquads + TILE - 1) / TILE;   // 8192

    // reset the tile counter (captured as a memset node; no allocation)
    void* ctr_addr = nullptr;
    cudaGetSymbolAddress(&ctr_addr, g_ctr);
    cudaMemsetAsync(ctr_addr, 0, sizeof(int));

    // one wave: 148 SMs x 8 resident 256-thread blocks (regs forced <=32)
    int blocks = 148 * 8;
    if (blocks > ntiles) blocks = ntiles;

    scatter_gcn<<<blocks, TPB>>>(gs, emb, A, W0, W1, W2, Wf, bf, out,
                                 nquads, ntiles);
}

// round 15
// speedup vs baseline: 8.5547x; 1.0031x over previous
#include <cuda_runtime.h>
#include <cuda_bf16.h>

#define N_NODES 5
#define EMB 16
#define HID 32

// ---------------------------------------------------------------------------
// Single fused PERSISTENT kernel, one wave, WARP-AUTONOMOUS streaming.
// Prologue (once per block): 5-node GCN -> 6x16 LUT in smem; weights staged
//   transposed+padded so every LDS is bank-conflict-free.
// Main: each WARP independently walks 256-quad warp-tiles with a static
//   stride — zero barriers, zero atomics, zero shared state in the loop, so
//   no warp ever gates another at a tile boundary (R14's per-tile
//   __syncthreads made each block's slowest warp gate the other 7).
//   Lane l handles quads {base + l + u*32}: each step is a fully-coalesced
//   512B/warp STG.128 stream via __stcs. 65536 warp-tiles / 9472 warps.
// ---------------------------------------------------------------------------
#define TPB 256
#define QPT 8
#define WTILE (32 * QPT)   // 256 quads per warp-tile

__global__ void __launch_bounds__(TPB, 8)
scatter_gcn(const int* __restrict__ gs,
            const float* __restrict__ emb,   // [5,16]
            const float* __restrict__ A,     // [5,5]
            const float* __restrict__ W0,    // [32,16]
            const float* __restrict__ W1,    // [32,32]
            const float* __restrict__ W2,    // [32,32]
            const float* __restrict__ Wf,    // [16,32]
            const float* __restrict__ bf,    // [16]
            float4* __restrict__ out,
            int nquads, int nwtiles)
{
    __shared__ float sE[N_NODES * EMB];
    __shared__ float sA[N_NODES * N_NODES];
    __shared__ float sW0T[EMB * 33];           // W0T[j][o]
    __shared__ float sW1T[HID * 33];           // W1T[j][o]
    __shared__ float sW2T[HID * 33];           // W2T[j][o]
    __shared__ float sWfT[HID * 17];           // WfT[j][e]
    __shared__ float sbf[EMB];
    __shared__ float x0[N_NODES][EMB];
    __shared__ float h[N_NODES][HID];
    __shared__ float y[N_NODES][HID];
    __shared__ float4 slut[6 * 4];             // final LUT: 6 rows x 4 quads

    const int t = threadIdx.x;

    // ---- stage weights (conflict-free transposed STS) ----
    for (int i = t; i < N_NODES * EMB; i += TPB) sE[i] = emb[i];
    for (int i = t; i < N_NODES * N_NODES; i += TPB) sA[i] = A[i];
    for (int i = t; i < HID * EMB; i += TPB) {
        int o = i / EMB, j = i % EMB;
        sW0T[j * 33 + o] = W0[i];
    }
    for (int i = t; i < HID * HID; i += TPB) {
        int o = i / HID, j = i % HID;
        sW1T[j * 33 + o] = W1[i];
    }
    for (int i = t; i < HID * HID; i += TPB) {
        int o = i / HID, j = i % HID;
        sW2T[j * 33 + o] = W2[i];
    }
    for (int i = t; i < EMB * HID; i += TPB) {
        int e = i / HID, j = i % HID;
        sWfT[j * 17 + e] = Wf[i];
    }
    for (int i = t; i < EMB; i += TPB) sbf[i] = bf[i];
    __syncthreads();

    // ---- GCN stages (all LDS conflict-free) ----
    if (t < N_NODES * EMB) {
        int i = t / EMB, j = t % EMB;
        float s = 0.f;
        #pragma unroll
        for (int k = 0; k < N_NODES; k++) s += sA[i * N_NODES + k] * sE[k * EMB + j];
        x0[i][j] = s;
    }
    __syncthreads();

    if (t < N_NODES * HID) {
        int i = t / HID, o = t % HID;
        float s = 0.f;
        #pragma unroll
        for (int j = 0; j < EMB; j++) s += x0[i][j] * sW0T[j * 33 + o];
        h[i][o] = fmaxf(s, 0.f);
    }
    __syncthreads();

    if (t < N_NODES * HID) {
        int i = t / HID, o = t % HID;
        float s = 0.f;
        #pragma unroll
        for (int k = 0; k < N_NODES; k++) s += sA[i * N_NODES + k] * h[k][o];
        y[i][o] = s;
    }
    __syncthreads();
    if (t < N_NODES * HID) {
        int i = t / HID, o = t % HID;
        float s = 0.f;
        #pragma unroll
        for (int j = 0; j < HID; j++) s += y[i][j] * sW1T[j * 33 + o];
        h[i][o] = fmaxf(s, 0.f);
    }
    __syncthreads();

    if (t < N_NODES * HID) {
        int i = t / HID, o = t % HID;
        float s = 0.f;
        #pragma unroll
        for (int k = 0; k < N_NODES; k++) s += sA[i * N_NODES + k] * h[k][o];
        y[i][o] = s;
    }
    __syncthreads();
    if (t < N_NODES * HID) {
        int i = t / HID, o = t % HID;
        float s = 0.f;
        #pragma unroll
        for (int j = 0; j < HID; j++) s += y[i][j] * sW2T[j * 33 + o];
        h[i][o] = fmaxf(s, 0.f);
    }
    __syncthreads();

    float* slutf = reinterpret_cast<float*>(slut);
    if (t < N_NODES * EMB) {
        int i = t / EMB, e = t % EMB;
        float s = sbf[e];
        #pragma unroll
        for (int j = 0; j < HID; j++) s += h[i][j] * sWfT[j * 17 + e];
        slutf[(i + 1) * EMB + e] = s;
    }
    if (t < EMB) slutf[t] = sE[t];
    __syncthreads();   // LUT ready — last block-wide sync in the kernel

    // ---- warp-autonomous streaming loop (no barriers, no atomics) ----
    const int lane = t & 31;
    const int gwarp = blockIdx.x * (TPB / 32) + (t >> 5);   // 0..9471
    const int nwarps = gridDim.x * (TPB / 32);
    const int q = lane & 3;                                 // lane-within-cell
    const float4* __restrict__ lutq = slut + q;

    for (int wt = gwarp; wt < nwtiles; wt += nwarps) {
        const int base = wt * WTILE + lane;
        float4* __restrict__ o = out + base;

        if (base + (QPT - 1) * 32 < nquads) {
            // fast path: 8 independent gs loads, then 8 coalesced 512B stores
            const int* __restrict__ g = gs + (base >> 2);
            int c[QPT];
            #pragma unroll
            for (int u = 0; u < QPT; u++) c[u] = __ldg(g + u * 8);
            #pragma unroll
            for (int u = 0; u < QPT; u++) {
                float4 v = lutq[c[u] * 4];
                __stcs(o + u * 32, v);
            }
        } else {
            #pragma unroll
            for (int u = 0; u < QPT; u++) {
                int idx = base + u * 32;
                if (idx < nquads) {
                    int cc = __ldg(gs + (idx >> 2));
                    __stcs(o + u * 32, lutq[cc * 4]);
                }
            }
        }
    }
}

// ---------------------------------------------------------------------------
extern "C" void kernel_launch(void* const* d_in, const int* in_sizes, int n_in,
                              void* d_out, int out_size)
{
    const int*   gs  = (const int*)d_in[0];    // game_state [256,128,128]
    const float* emb = (const float*)d_in[1];  // [5,16]
    const float* A   = (const float*)d_in[2];  // [5,5]
    const float* W0  = (const float*)d_in[3];  // [32,16]
    const float* W1  = (const float*)d_in[4];  // [32,32]
    const float* W2  = (const float*)d_in[5];  // [32,32]
    const float* Wf  = (const float*)d_in[6];  // [16,32]
    const float* bf  = (const float*)d_in[7];  // [16]
    float4* out = (float4*)d_out;

    const int ncells  = in_sizes[0];           // 4,194,304
    const int nquads  = ncells * 4;            // 16,777,216 float4 stores
    const int nwtiles = (nquads + WTILE - 1) / WTILE;   // 65,536

    // one wave: 148 SMs x 8 resident 256-thread blocks (regs forced <=32)
    int blocks = 148 * 8;

    scatter_gcn<<<blocks, TPB>>>(gs, emb, A, W0, W1, W2, Wf, bf, out,
                                 nquads, nwtiles);
}